// round 2
// baseline (speedup 1.0000x reference)
#include <cuda_runtime.h>
#include <cstddef>

// Problem constants (fixed by the reference):
//   B=4096, T=256, I=6, H=64, gates = 3H = 192, 2 GRU layers + FC(H->1)
#define T_STEPS 256
#define I_DIM   6
#define HDIM    64
#define G3      192
#define BB      32      // batches per CTA
#define NT      512     // threads per CTA
#define PW      68      // weight row pitch (floats): 68 mod 32 == 4 -> conflict-free LDS.128
#define NCTA    128     // 4096 / 32

struct SmemLayout {
    float Whh0[G3 * PW];    // layer0 recurrent weights [gate][k]
    float Wih1[G3 * PW];    // layer1 input weights
    float Whh1[G3 * PW];    // layer1 recurrent weights
    float Wih0[G3 * 8];     // layer0 input weights (6 cols, pitch 8)
    float bih0[G3];
    float bhh0[G3];
    float bih1[G3];
    float bhh1[G3];
    float h1[2][BB][HDIM];  // ping-pong hidden state, layer 0
    float h2[2][BB][HDIM];  // ping-pong hidden state, layer 1
    float xs[2][BB][I_DIM]; // double-buffered x_t staging
    float wfc[HDIM];
    float bfc;
};

__device__ __forceinline__ float sigf(float v) {
    return __fdividef(1.0f, 1.0f + __expf(-v));
}

__global__ __launch_bounds__(NT, 1) void gru_fused_kernel(
    const float* __restrict__ x,
    const float* __restrict__ W_ih0, const float* __restrict__ W_hh0,
    const float* __restrict__ b_ih0, const float* __restrict__ b_hh0,
    const float* __restrict__ W_ih1, const float* __restrict__ W_hh1,
    const float* __restrict__ b_ih1, const float* __restrict__ b_hh1,
    const float* __restrict__ W_fc,  const float* __restrict__ b_fc,
    float* __restrict__ out)
{
    extern __shared__ float smem_raw[];
    SmemLayout& s = *reinterpret_cast<SmemLayout*>(smem_raw);

    const int tid = threadIdx.x;
    const int b0  = blockIdx.x * BB;   // global batch base for this CTA

    // ---- Stage weights into SMEM (coalesced reads, padded rows) ----
    for (int i = tid; i < G3 * HDIM; i += NT) {
        int r = i >> 6, c = i & 63;
        s.Whh0[r * PW + c] = W_hh0[i];
        s.Wih1[r * PW + c] = W_ih1[i];
        s.Whh1[r * PW + c] = W_hh1[i];
    }
    for (int i = tid; i < G3 * I_DIM; i += NT)
        s.Wih0[(i / I_DIM) * 8 + (i % I_DIM)] = W_ih0[i];
    for (int i = tid; i < G3; i += NT) {
        s.bih0[i] = b_ih0[i];
        s.bhh0[i] = b_hh0[i];
        s.bih1[i] = b_ih1[i];
        s.bhh1[i] = b_hh1[i];
    }
    for (int i = tid; i < BB * HDIM; i += NT) {
        int b = i >> 6, c = i & 63;
        s.h1[0][b][c] = 0.0f;
        s.h2[0][b][c] = 0.0f;
    }
    if (tid < HDIM) s.wfc[tid] = W_fc[tid];
    if (tid == 0)   s.bfc = b_fc[0];

    // x prefetch lane assignment (fixed for the whole time loop)
    const bool is_pref_lane = (tid < BB * I_DIM);
    const int  lb = is_pref_lane ? (tid / I_DIM) : 0;
    const int  li = is_pref_lane ? (tid % I_DIM) : 0;
    const float* xlane = x + (size_t)(b0 + lb) * T_STEPS * I_DIM + li;

    // x for t = 0
    if (is_pref_lane) s.xs[0][lb][li] = xlane[0];
    __syncthreads();

    // Thread mapping: gg = hidden unit (0..63), bg = 4-batch group (0..7).
    // Thread handles gates {gg, gg+64, gg+128} = (r,z,n) for unit gg,
    // for batches bb0..bb0+3. A warp shares bg -> h loads are broadcasts;
    // weight rows are lane-consecutive -> conflict-free LDS.128 with PW=68.
    const int gg  = tid & 63;
    const int bg  = tid >> 6;
    const int bb0 = bg * 4;
    const int gr = gg, gz = gg + 64, gn = gg + 128;

    for (int t = 0; t < T_STEPS; ++t) {
        const int cur = t & 1, nxt = cur ^ 1;

        // Prefetch x for t+1 (latency hidden under ~10K cycles of FMA)
        float xpref = 0.0f;
        const bool do_pref = is_pref_lane && (t + 1 < T_STEPS);
        if (do_pref) xpref = xlane[(size_t)(t + 1) * I_DIM];

        // ================= Layer 0 =================
        float aX[4][3], aH[4][3];
        {
            const float bi0 = s.bih0[gr], bi1 = s.bih0[gz], bi2 = s.bih0[gn];
            const float bh0 = s.bhh0[gr], bh1 = s.bhh0[gz], bh2 = s.bhh0[gn];
            #pragma unroll
            for (int b = 0; b < 4; ++b) {
                aX[b][0] = bi0; aX[b][1] = bi1; aX[b][2] = bi2;
                aH[b][0] = bh0; aH[b][1] = bh1; aH[b][2] = bh2;
            }
        }
        #pragma unroll 4
        for (int k = 0; k < HDIM; k += 4) {
            float4 w0 = *(const float4*)&s.Whh0[gr * PW + k];
            float4 w1 = *(const float4*)&s.Whh0[gz * PW + k];
            float4 w2 = *(const float4*)&s.Whh0[gn * PW + k];
            #pragma unroll
            for (int b = 0; b < 4; ++b) {
                float4 h4 = *(const float4*)&s.h1[cur][bb0 + b][k];
                aH[b][0] = fmaf(h4.x, w0.x, fmaf(h4.y, w0.y, fmaf(h4.z, w0.z, fmaf(h4.w, w0.w, aH[b][0]))));
                aH[b][1] = fmaf(h4.x, w1.x, fmaf(h4.y, w1.y, fmaf(h4.z, w1.z, fmaf(h4.w, w1.w, aH[b][1]))));
                aH[b][2] = fmaf(h4.x, w2.x, fmaf(h4.y, w2.y, fmaf(h4.z, w2.z, fmaf(h4.w, w2.w, aH[b][2]))));
            }
        }
        #pragma unroll
        for (int k = 0; k < I_DIM; ++k) {
            float w0 = s.Wih0[gr * 8 + k];
            float w1 = s.Wih0[gz * 8 + k];
            float w2 = s.Wih0[gn * 8 + k];
            #pragma unroll
            for (int b = 0; b < 4; ++b) {
                float xv = s.xs[cur][bb0 + b][k];
                aX[b][0] = fmaf(xv, w0, aX[b][0]);
                aX[b][1] = fmaf(xv, w1, aX[b][1]);
                aX[b][2] = fmaf(xv, w2, aX[b][2]);
            }
        }
        #pragma unroll
        for (int b = 0; b < 4; ++b) {
            float r = sigf(aX[b][0] + aH[b][0]);
            float z = sigf(aX[b][1] + aH[b][1]);
            float n = tanhf(fmaf(r, aH[b][2], aX[b][2]));
            float hp = s.h1[cur][bb0 + b][gg];
            s.h1[nxt][bb0 + b][gg] = fmaf(z, hp - n, n);   // (1-z)n + z h
        }
        if (do_pref) s.xs[nxt][lb][li] = xpref;
        __syncthreads();   // h1[nxt] complete

        // ================= Layer 1 =================
        // input = h1[nxt] (just produced), recurrent state = h2[cur]
        {
            const float bi0 = s.bih1[gr], bi1 = s.bih1[gz], bi2 = s.bih1[gn];
            const float bh0 = s.bhh1[gr], bh1 = s.bhh1[gz], bh2 = s.bhh1[gn];
            #pragma unroll
            for (int b = 0; b < 4; ++b) {
                aX[b][0] = bi0; aX[b][1] = bi1; aX[b][2] = bi2;
                aH[b][0] = bh0; aH[b][1] = bh1; aH[b][2] = bh2;
            }
        }
        #pragma unroll 2
        for (int k = 0; k < HDIM; k += 4) {
            float4 u0 = *(const float4*)&s.Wih1[gr * PW + k];
            float4 u1 = *(const float4*)&s.Wih1[gz * PW + k];
            float4 u2 = *(const float4*)&s.Wih1[gn * PW + k];
            float4 v0 = *(const float4*)&s.Whh1[gr * PW + k];
            float4 v1 = *(const float4*)&s.Whh1[gz * PW + k];
            float4 v2 = *(const float4*)&s.Whh1[gn * PW + k];
            #pragma unroll
            for (int b = 0; b < 4; ++b) {
                float4 p4 = *(const float4*)&s.h1[nxt][bb0 + b][k];
                float4 q4 = *(const float4*)&s.h2[cur][bb0 + b][k];
                aX[b][0] = fmaf(p4.x, u0.x, fmaf(p4.y, u0.y, fmaf(p4.z, u0.z, fmaf(p4.w, u0.w, aX[b][0]))));
                aX[b][1] = fmaf(p4.x, u1.x, fmaf(p4.y, u1.y, fmaf(p4.z, u1.z, fmaf(p4.w, u1.w, aX[b][1]))));
                aX[b][2] = fmaf(p4.x, u2.x, fmaf(p4.y, u2.y, fmaf(p4.z, u2.z, fmaf(p4.w, u2.w, aX[b][2]))));
                aH[b][0] = fmaf(q4.x, v0.x, fmaf(q4.y, v0.y, fmaf(q4.z, v0.z, fmaf(q4.w, v0.w, aH[b][0]))));
                aH[b][1] = fmaf(q4.x, v1.x, fmaf(q4.y, v1.y, fmaf(q4.z, v1.z, fmaf(q4.w, v1.w, aH[b][1]))));
                aH[b][2] = fmaf(q4.x, v2.x, fmaf(q4.y, v2.y, fmaf(q4.z, v2.z, fmaf(q4.w, v2.w, aH[b][2]))));
            }
        }
        #pragma unroll
        for (int b = 0; b < 4; ++b) {
            float r = sigf(aX[b][0] + aH[b][0]);
            float z = sigf(aX[b][1] + aH[b][1]);
            float n = tanhf(fmaf(r, aH[b][2], aX[b][2]));
            float hp = s.h2[cur][bb0 + b][gg];
            s.h2[nxt][bb0 + b][gg] = fmaf(z, hp - n, n);
        }
        __syncthreads();   // h2[nxt] complete; buffers swap
    }

    // ---- Final FC: out[b] = h2_last[b] . W_fc + b_fc ----
    const int fin = T_STEPS & 1;   // after 256 steps, latest state is buffer 0
    if (tid < BB) {
        float acc = s.bfc;
        #pragma unroll 8
        for (int k = 0; k < HDIM; ++k)
            acc = fmaf(s.h2[fin][tid][k], s.wfc[k], acc);
        out[b0 + tid] = acc;
    }
}

extern "C" void kernel_launch(void* const* d_in, const int* in_sizes, int n_in,
                              void* d_out, int out_size)
{
    const float* x     = (const float*)d_in[0];
    const float* W_ih0 = (const float*)d_in[1];
    const float* W_hh0 = (const float*)d_in[2];
    const float* b_ih0 = (const float*)d_in[3];
    const float* b_hh0 = (const float*)d_in[4];
    const float* W_ih1 = (const float*)d_in[5];
    const float* W_hh1 = (const float*)d_in[6];
    const float* b_ih1 = (const float*)d_in[7];
    const float* b_hh1 = (const float*)d_in[8];
    const float* W_fc  = (const float*)d_in[9];
    const float* b_fc  = (const float*)d_in[10];
    float* out = (float*)d_out;

    (void)in_sizes; (void)n_in; (void)out_size;

    static_assert(sizeof(SmemLayout) < 227 * 1024, "smem over budget");
    cudaFuncSetAttribute(gru_fused_kernel,
                         cudaFuncAttributeMaxDynamicSharedMemorySize,
                         (int)sizeof(SmemLayout));

    gru_fused_kernel<<<NCTA, NT, sizeof(SmemLayout)>>>(
        x, W_ih0, W_hh0, b_ih0, b_hh0,
        W_ih1, W_hh1, b_ih1, b_hh1,
        W_fc, b_fc, out);
}

// round 3
// speedup vs baseline: 1.2236x; 1.2236x over previous
#include <cuda_runtime.h>
#include <cstddef>

// Problem constants: B=4096, T=256, I=6, H=64, gates=3H=192, 2 GRU layers + FC
#define T_STEPS 256
#define I_DIM   6
#define HDIM    64
#define G3      192
#define BB      32      // batches per CTA
#define NT      256     // threads per CTA (64 units x 4 batch-groups)
#define NBPT    8       // batches per thread
#define PW      68      // weight row pitch (floats): conflict-free LDS.128
#define NCTA    128     // 4096 / 32

typedef unsigned long long u64;

// Packed fp32x2 FMA: acc.{x,y} += a.{x,y} * b.{x,y}  (SASS FFMA2, PTX-only)
#define FFMA2(acc, a, b) \
    asm("fma.rn.f32x2 %0, %1, %2, %0;" : "+l"(acc) : "l"(a), "l"(b))

union F4U { float4 f; u64 u[2]; };
union F2U { float2 f; u64 u; };

struct SmemLayout {
    float Whh0[G3 * PW];
    float Wih1[G3 * PW];
    float Whh1[G3 * PW];
    float Wih0[G3 * 8];     // pitch 8 (I=6 used) -> float2-aligned pairs
    float bih0[G3];
    float bhh0[G3];
    float bih1[G3];
    float bhh1[G3];
    float h1[2][BB][HDIM];
    float h2[2][BB][HDIM];
    float xs[2][BB][8];     // pitch 8 for float2 pairing
    float wfc[HDIM];
    float bfc;
};

__device__ __forceinline__ float sigf(float v) {
    return __fdividef(1.0f, 1.0f + __expf(-v));
}

__device__ __forceinline__ float hsum(u64 p, float bias) {
    F2U t; t.u = p;
    return t.f.x + t.f.y + bias;
}

__global__ __launch_bounds__(NT, 1) void gru_fused_kernel(
    const float* __restrict__ x,
    const float* __restrict__ W_ih0, const float* __restrict__ W_hh0,
    const float* __restrict__ b_ih0, const float* __restrict__ b_hh0,
    const float* __restrict__ W_ih1, const float* __restrict__ W_hh1,
    const float* __restrict__ b_ih1, const float* __restrict__ b_hh1,
    const float* __restrict__ W_fc,  const float* __restrict__ b_fc,
    float* __restrict__ out)
{
    extern __shared__ float smem_raw[];
    SmemLayout& s = *reinterpret_cast<SmemLayout*>(smem_raw);

    const int tid = threadIdx.x;
    const int b0  = blockIdx.x * BB;

    // ---- Stage weights into SMEM ----
    for (int i = tid; i < G3 * HDIM; i += NT) {
        int r = i >> 6, c = i & 63;
        s.Whh0[r * PW + c] = W_hh0[i];
        s.Wih1[r * PW + c] = W_ih1[i];
        s.Whh1[r * PW + c] = W_hh1[i];
    }
    for (int i = tid; i < G3 * 8; i += NT) s.Wih0[i] = 0.0f;   // pad
    for (int i = tid; i < BB * 8 * 2; i += NT)
        ((float*)s.xs)[i] = 0.0f;                              // pad
    __syncthreads();
    for (int i = tid; i < G3 * I_DIM; i += NT)
        s.Wih0[(i / I_DIM) * 8 + (i % I_DIM)] = W_ih0[i];
    for (int i = tid; i < G3; i += NT) {
        s.bih0[i] = b_ih0[i];
        s.bhh0[i] = b_hh0[i];
        s.bih1[i] = b_ih1[i];
        s.bhh1[i] = b_hh1[i];
    }
    for (int i = tid; i < BB * HDIM; i += NT) {
        int b = i >> 6, c = i & 63;
        s.h1[0][b][c] = 0.0f;
        s.h2[0][b][c] = 0.0f;
    }
    if (tid < HDIM) s.wfc[tid] = W_fc[tid];
    if (tid == 0)   s.bfc = b_fc[0];

    // x prefetch lanes (one per (batch, input-dim))
    const bool is_pref_lane = (tid < BB * I_DIM);
    const int  lb = is_pref_lane ? (tid / I_DIM) : 0;
    const int  li = is_pref_lane ? (tid % I_DIM) : 0;
    const float* xlane = x + (size_t)(b0 + lb) * T_STEPS * I_DIM + li;
    if (is_pref_lane) s.xs[0][lb][li] = xlane[0];
    __syncthreads();

    // Mapping: gg = hidden unit (0..63); bg = tid>>6 (0..3) -> 8 batches each.
    const int gg  = tid & 63;
    const int bg  = tid >> 6;
    const int bb0 = bg * NBPT;
    const int gr = gg, gz = gg + 64, gn = gg + 128;

    const float bi0r = s.bih0[gr], bi0z = s.bih0[gz], bi0n = s.bih0[gn];
    const float bh0r = s.bhh0[gr], bh0z = s.bhh0[gz], bh0n = s.bhh0[gn];
    const float bi1r = s.bih1[gr], bi1z = s.bih1[gz], bi1n = s.bih1[gn];
    const float bh1r = s.bhh1[gr], bh1z = s.bhh1[gz], bh1n = s.bhh1[gn];

    u64 accX[NBPT][3], accH[NBPT][3];

    for (int t = 0; t < T_STEPS; ++t) {
        const int cur = t & 1, nxt = cur ^ 1;

        float xpref = 0.0f;
        const bool do_pref = is_pref_lane && (t + 1 < T_STEPS);
        if (do_pref) xpref = xlane[(size_t)(t + 1) * I_DIM];

        // ================= Layer 0 =================
        #pragma unroll
        for (int b = 0; b < NBPT; ++b) {
            accX[b][0] = 0ull; accX[b][1] = 0ull; accX[b][2] = 0ull;
            accH[b][0] = 0ull; accH[b][1] = 0ull; accH[b][2] = 0ull;
        }
        // recurrent GEMV: packed over k-pairs
        #pragma unroll 2
        for (int k = 0; k < HDIM; k += 4) {
            F4U w0; w0.f = *(const float4*)&s.Whh0[gr * PW + k];
            F4U w1; w1.f = *(const float4*)&s.Whh0[gz * PW + k];
            F4U w2; w2.f = *(const float4*)&s.Whh0[gn * PW + k];
            #pragma unroll
            for (int b = 0; b < NBPT; ++b) {
                F4U h; h.f = *(const float4*)&s.h1[cur][bb0 + b][k];
                FFMA2(accH[b][0], h.u[0], w0.u[0]);
                FFMA2(accH[b][0], h.u[1], w0.u[1]);
                FFMA2(accH[b][1], h.u[0], w1.u[0]);
                FFMA2(accH[b][1], h.u[1], w1.u[1]);
                FFMA2(accH[b][2], h.u[0], w2.u[0]);
                FFMA2(accH[b][2], h.u[1], w2.u[1]);
            }
        }
        // input GEMV: I=6 -> 3 packed pairs (padded lane 6,7 are zero)
        #pragma unroll
        for (int kp = 0; kp < 3; ++kp) {
            F2U w0; w0.f = *(const float2*)&s.Wih0[gr * 8 + 2 * kp];
            F2U w1; w1.f = *(const float2*)&s.Wih0[gz * 8 + 2 * kp];
            F2U w2; w2.f = *(const float2*)&s.Wih0[gn * 8 + 2 * kp];
            #pragma unroll
            for (int b = 0; b < NBPT; ++b) {
                F2U xv; xv.f = *(const float2*)&s.xs[cur][bb0 + b][2 * kp];
                FFMA2(accX[b][0], xv.u, w0.u);
                FFMA2(accX[b][1], xv.u, w1.u);
                FFMA2(accX[b][2], xv.u, w2.u);
            }
        }
        #pragma unroll
        for (int b = 0; b < NBPT; ++b) {
            float r = sigf(hsum(accX[b][0], bi0r) + hsum(accH[b][0], bh0r));
            float z = sigf(hsum(accX[b][1], bi0z) + hsum(accH[b][1], bh0z));
            float n = tanhf(fmaf(r, hsum(accH[b][2], bh0n), hsum(accX[b][2], bi0n)));
            float hp = s.h1[cur][bb0 + b][gg];
            s.h1[nxt][bb0 + b][gg] = fmaf(z, hp - n, n);
        }
        if (do_pref) s.xs[nxt][lb][li] = xpref;
        __syncthreads();   // h1[nxt] complete

        // ================= Layer 1 =================
        #pragma unroll
        for (int b = 0; b < NBPT; ++b) {
            accX[b][0] = 0ull; accX[b][1] = 0ull; accX[b][2] = 0ull;
            accH[b][0] = 0ull; accH[b][1] = 0ull; accH[b][2] = 0ull;
        }
        #pragma unroll 2
        for (int k = 0; k < HDIM; k += 4) {
            F4U u0; u0.f = *(const float4*)&s.Wih1[gr * PW + k];
            F4U u1; u1.f = *(const float4*)&s.Wih1[gz * PW + k];
            F4U u2; u2.f = *(const float4*)&s.Wih1[gn * PW + k];
            F4U v0; v0.f = *(const float4*)&s.Whh1[gr * PW + k];
            F4U v1; v1.f = *(const float4*)&s.Whh1[gz * PW + k];
            F4U v2; v2.f = *(const float4*)&s.Whh1[gn * PW + k];
            #pragma unroll
            for (int b = 0; b < NBPT; ++b) {
                F4U p; p.f = *(const float4*)&s.h1[nxt][bb0 + b][k];
                F4U q; q.f = *(const float4*)&s.h2[cur][bb0 + b][k];
                FFMA2(accX[b][0], p.u[0], u0.u[0]);
                FFMA2(accX[b][0], p.u[1], u0.u[1]);
                FFMA2(accX[b][1], p.u[0], u1.u[0]);
                FFMA2(accX[b][1], p.u[1], u1.u[1]);
                FFMA2(accX[b][2], p.u[0], u2.u[0]);
                FFMA2(accX[b][2], p.u[1], u2.u[1]);
                FFMA2(accH[b][0], q.u[0], v0.u[0]);
                FFMA2(accH[b][0], q.u[1], v0.u[1]);
                FFMA2(accH[b][1], q.u[0], v1.u[0]);
                FFMA2(accH[b][1], q.u[1], v1.u[1]);
                FFMA2(accH[b][2], q.u[0], v2.u[0]);
                FFMA2(accH[b][2], q.u[1], v2.u[1]);
            }
        }
        #pragma unroll
        for (int b = 0; b < NBPT; ++b) {
            float r = sigf(hsum(accX[b][0], bi1r) + hsum(accH[b][0], bh1r));
            float z = sigf(hsum(accX[b][1], bi1z) + hsum(accH[b][1], bh1z));
            float n = tanhf(fmaf(r, hsum(accH[b][2], bh1n), hsum(accX[b][2], bi1n)));
            float hp = s.h2[cur][bb0 + b][gg];
            s.h2[nxt][bb0 + b][gg] = fmaf(z, hp - n, n);
        }
        __syncthreads();   // h2[nxt] complete
    }

    // ---- Final FC ----
    const int fin = T_STEPS & 1;
    if (tid < BB) {
        float acc = s.bfc;
        #pragma unroll 8
        for (int k = 0; k < HDIM; ++k)
            acc = fmaf(s.h2[fin][tid][k], s.wfc[k], acc);
        out[b0 + tid] = acc;
    }
}

extern "C" void kernel_launch(void* const* d_in, const int* in_sizes, int n_in,
                              void* d_out, int out_size)
{
    const float* x     = (const float*)d_in[0];
    const float* W_ih0 = (const float*)d_in[1];
    const float* W_hh0 = (const float*)d_in[2];
    const float* b_ih0 = (const float*)d_in[3];
    const float* b_hh0 = (const float*)d_in[4];
    const float* W_ih1 = (const float*)d_in[5];
    const float* W_hh1 = (const float*)d_in[6];
    const float* b_ih1 = (const float*)d_in[7];
    const float* b_hh1 = (const float*)d_in[8];
    const float* W_fc  = (const float*)d_in[9];
    const float* b_fc  = (const float*)d_in[10];
    float* out = (float*)d_out;

    (void)in_sizes; (void)n_in; (void)out_size;

    static_assert(sizeof(SmemLayout) < 227 * 1024, "smem over budget");
    cudaFuncSetAttribute(gru_fused_kernel,
                         cudaFuncAttributeMaxDynamicSharedMemorySize,
                         (int)sizeof(SmemLayout));

    gru_fused_kernel<<<NCTA, NT, sizeof(SmemLayout)>>>(
        x, W_ih0, W_hh0, b_ih0, b_hh0,
        W_ih1, W_hh1, b_ih1, b_hh1,
        W_fc, b_fc, out);
}